// round 14
// baseline (speedup 1.0000x reference)
#include <cuda_runtime.h>
#include <cuda_bf16.h>
#include <cuda_fp16.h>
#include <cstdint>
#include <cstring>
#include <math.h>

#define DIN  512
#define DOUT 128
#define MAXN 100000
#define MAXE 3200000

// ---------------- device-global scratch (no runtime allocation) ------------
__device__ __align__(16) __half g_xph[(size_t)MAXN * DOUT];    // projected X, fp16
__device__ __align__(16) float g_G[DOUT * DOUT];               // gram -> chol -> inv(L)
__device__ __align__(16) __nv_bfloat16 g_wth[DOUT * DIN];      // W_ortho^T hi  [n][k]
__device__ __align__(16) __nv_bfloat16 g_wtl[DOUT * DIN];      // W_ortho^T lo  [n][k]
__device__ int   g_deg[MAXN];
__device__ int   g_rowptr[MAXN];
__device__ int   g_cursor[MAXN];
__device__ int   g_total;
__device__ __align__(8) int2 g_edge[MAXE];                     // .x=col .y=val bits

__device__ __forceinline__ uint32_t pack_bf16(__nv_bfloat16 a, __nv_bfloat16 b) {
    __nv_bfloat162 t(a, b);
    uint32_t r; memcpy(&r, &t, 4); return r;
}

__device__ __forceinline__ uint32_t smem_u32(const void* p) {
    return (uint32_t)__cvta_generic_to_shared(p);
}

// async 16B copy, L1-bypass
__device__ __forceinline__ void cp16(uint32_t s, const void* g) {
    asm volatile("cp.async.cg.shared.global [%0], [%1], 16;" :: "r"(s), "l"(g));
}
#define CP_COMMIT() asm volatile("cp.async.commit_group;")
#define CP_WAIT0()  asm volatile("cp.async.wait_group 0;")

// warp-level bf16 MMA (sm_80+; compiles on plain sm_100 target)
__device__ __forceinline__ void mma16816(float* d, const uint32_t* a, const uint32_t* b) {
    asm volatile("mma.sync.aligned.m16n8k16.row.col.f32.bf16.bf16.f32 "
        "{%0,%1,%2,%3}, {%4,%5,%6,%7}, {%8,%9}, {%0,%1,%2,%3};"
        : "+f"(d[0]), "+f"(d[1]), "+f"(d[2]), "+f"(d[3])
        : "r"(a[0]), "r"(a[1]), "r"(a[2]), "r"(a[3]), "r"(b[0]), "r"(b[1]));
}

__device__ __forceinline__ void ldm_x4(uint32_t* r, uint32_t addr) {
    asm volatile("ldmatrix.sync.aligned.m8n8.x4.shared.b16 {%0,%1,%2,%3}, [%4];"
        : "=r"(r[0]), "=r"(r[1]), "=r"(r[2]), "=r"(r[3]) : "r"(addr));
}

// XOR swizzle on 64B rows packed in 128B lines: bits[4:6] ^= bits[7:9]
__device__ __forceinline__ uint32_t swz(uint32_t off) {
    return off ^ ((off >> 3) & 0x70);
}

// ---------------- kA: Gram matrix + zero deg/total ---------------------------
__global__ void __launch_bounds__(128) kA(const float* __restrict__ W, int n) {
    if (blockIdx.x < DOUT) {
        __shared__ float col[DIN];
        int i = blockIdx.x, j = threadIdx.x;
        for (int k = j; k < DIN; k += DOUT) col[k] = W[k * DOUT + i];
        __syncthreads();
        float acc = 0.f;
        #pragma unroll 8
        for (int k = 0; k < DIN; k++) acc = fmaf(col[k], W[k * DOUT + j], acc);
        g_G[i * DOUT + j] = acc + (i == j ? 1e-4f : 0.f);
    } else {
        if (blockIdx.x == DOUT && threadIdx.x == 0) g_total = 0;
        int i = (blockIdx.x - DOUT) * 128 + threadIdx.x;
        if (i < n) g_deg[i] = 0;
    }
}

// ---------------- Cholesky + triangular inverse (fused, one block) ----------
// Phase 1: in-smem Cholesky (4 threads/row).  Phase 2: M = inv(L), column-
// parallel (4 lanes per column, shfl-reduced).  g_G <- inv(L) (lower, rest 0).
static constexpr int CP_ = 129;
static constexpr int CI_SMEM = (2 * DOUT * CP_ + DOUT) * 4;   // Ls + Ms + diag

__global__ void __launch_bounds__(512) k_cholinv() {
    extern __shared__ float s[];
    float* Ls   = s;                        // 128 x pitch129
    float* Ms   = s + DOUT * CP_;           // 128 x pitch129
    float* diag = Ms + DOUT * CP_;          // L[i][i]
    int tid = threadIdx.x;
    int t = tid >> 2;        // row (chol) / column (inv), 0..127
    int q = tid & 3;

    for (int idx = tid; idx < DOUT * DOUT; idx += 512) {
        int r = idx >> 7, c = idx & 127;
        Ls[r * CP_ + c] = g_G[idx];
    }
    __syncthreads();

    // ---- Cholesky (diag of Ls stays pre-sqrt; true diag in diag[]) ----
    for (int k = 0; k < DOUT; k++) {
        float dk = sqrtf(Ls[k * CP_ + k]);
        if (tid == 0) diag[k] = dk;
        if (q == 0 && t > k) Ls[t * CP_ + k] /= dk;
        __syncthreads();
        if (t > k) {
            float lik = Ls[t * CP_ + k];
            for (int j = k + 1 + q; j <= t; j += 4)
                Ls[t * CP_ + j] -= lik * Ls[j * CP_ + k];
        }
        __syncthreads();
    }

    // ---- M = inv(L): column t, lanes q split the k-sum ----
    // M[i][i] = 1/L[i][i];  M[i][j] = -(1/L[i][i]) * sum_{k=j..i-1} L[i][k] M[k][j]
    for (int i = 0; i < DOUT; i++) {
        float p = 0.f;
        for (int k = t + q; k < i; k += 4)
            p = fmaf(Ls[i * CP_ + k], Ms[k * CP_ + t], p);
        p += __shfl_xor_sync(0xffffffffu, p, 1);
        p += __shfl_xor_sync(0xffffffffu, p, 2);
        if (q == 0) {
            if (t < i)       Ms[i * CP_ + t] = -p / diag[i];
            else if (t == i) Ms[i * CP_ + i] = 1.f / diag[i];
        }
        __syncthreads();
    }

    for (int idx = tid; idx < DOUT * DOUT; idx += 512) {
        int r = idx >> 7, c = idx & 127;
        g_G[idx] = (c <= r) ? Ms[r * CP_ + c] : 0.f;
    }
}

// ---------------- W_ortho = W @ inv(L)^T  (free-order, 16 blocks) -----------
// W_ortho[r][j] = sum_{k<=j} W[r][k] * M[j][k];  emit bf16 hi/lo at [n=j][k=r].
static constexpr int WP_ = 132;                       // W smem pitch (floats)
static constexpr int WO_SMEM = (DOUT * CP_ + 32 * WP_) * 4;   // 82944 B

__global__ void __launch_bounds__(256) k_wortho(const float* __restrict__ W) {
    extern __shared__ float s[];
    float* Ms = s;                  // 128 x pitch129 (inv(L))
    float* Ws = s + DOUT * CP_;     // 32 rows x pitch132
    int tid = threadIdx.x;
    int r0 = blockIdx.x * 32;

    for (int idx = tid; idx < DOUT * DOUT; idx += 256) {
        int r = idx >> 7, c = idx & 127;
        Ms[r * CP_ + c] = g_G[idx];
    }
    for (int idx = tid; idx < 32 * DOUT; idx += 256) {
        int rl = idx >> 7, c = idx & 127;
        Ws[rl * WP_ + c] = W[(size_t)(r0 + rl) * DOUT + c];
    }
    __syncthreads();

    int rl = tid >> 3;              // 0..31 local row
    int jq = tid & 7;               // j = jq + 8*jj  (conflict-free across warp)
    int r = r0 + rl;
    const float* wrow = Ws + rl * WP_;
    for (int jj = 0; jj < 16; jj++) {
        int j = jq + 8 * jj;
        const float* mrow = Ms + j * CP_;
        float s0 = 0.f, s1 = 0.f, s2 = 0.f, s3 = 0.f;
        int k = 0;
        for (; k + 3 <= j; k += 4) {
            s0 = fmaf(wrow[k],     mrow[k],     s0);
            s1 = fmaf(wrow[k + 1], mrow[k + 1], s1);
            s2 = fmaf(wrow[k + 2], mrow[k + 2], s2);
            s3 = fmaf(wrow[k + 3], mrow[k + 3], s3);
        }
        for (; k <= j; k++) s0 = fmaf(wrow[k], mrow[k], s0);
        float sv = (s0 + s1) + (s2 + s3);
        __nv_bfloat16 h = __float2bfloat16_rn(sv);
        g_wth[j * DIN + r] = h;
        g_wtl[j * DIN + r] = __float2bfloat16_rn(sv - __bfloat162float(h));
    }
}

// ---------------- GEMM: Xp = X @ W_ortho  (mma.sync bf16 hi/lo split) -------
static constexpr int TILE_B  = 128 * 64;            // 8192
static constexpr int STAGE_B = 4 * TILE_B;          // 32768 (Ah, Al, Bh, Bl)
static constexpr int GEMM_SMEM = 2 * STAGE_B;       // 65536

__global__ void __launch_bounds__(256, 2)
k_gemm(const float* __restrict__ X, int nn) {
    extern __shared__ char smem[];
    uint32_t sm0 = smem_u32(smem);
    int tid  = threadIdx.x;
    int lane = tid & 31;
    int wid  = tid >> 5;
    int warpm = wid & 3;
    int warpn = wid >> 2;
    int m0 = blockIdx.x * 128;

    float d[2][8][4];
    #pragma unroll
    for (int mf = 0; mf < 2; mf++)
        #pragma unroll
        for (int nf = 0; nf < 8; nf++)
            #pragma unroll
            for (int q = 0; q < 4; q++) d[mf][nf][q] = 0.f;

    int srow[4], skq[4];
    #pragma unroll
    for (int t = 0; t < 4; t++) {
        int idx = tid + t * 256;
        srow[t] = idx >> 3;
        skq[t]  = (idx & 7) << 2;
    }
    int brow[2], bq[2];
    #pragma unroll
    for (int t = 0; t < 2; t++) {
        int idx = tid + t * 256;
        brow[t] = idx >> 2;
        bq[t]   = (idx & 3) * 16;
    }

    uint32_t aoff[2][2];
    {
        int arow = warpm * 32 + ((lane >> 3) & 1) * 8 + (lane & 7);
        int akb  = (lane >> 4) << 4;
        #pragma unroll
        for (int mf = 0; mf < 2; mf++)
            #pragma unroll
            for (int ks = 0; ks < 2; ks++)
                aoff[mf][ks] = swz((uint32_t)((arow + mf * 16) * 64 + ks * 32 + akb));
    }
    uint32_t boff[4][2];
    {
        int bn  = warpn * 64 + ((lane >= 16) ? 8 : 0) + (lane & 7);
        int bkb = ((lane >> 3) & 1) * 16;
        #pragma unroll
        for (int np = 0; np < 4; np++)
            #pragma unroll
            for (int ks = 0; ks < 2; ks++)
                boff[np][ks] = swz((uint32_t)((bn + np * 16) * 64 + ks * 32 + bkb));
    }

    // ---- prologue: chunk 0 ----
    {
        uint32_t sBh = sm0 + 2 * TILE_B, sBl = sm0 + 3 * TILE_B;
        #pragma unroll
        for (int t = 0; t < 2; t++) {
            uint32_t off = swz((uint32_t)(brow[t] * 64 + bq[t]));
            cp16(sBh + off, (const char*)(g_wth + (size_t)brow[t] * DIN) + bq[t]);
            cp16(sBl + off, (const char*)(g_wtl + (size_t)brow[t] * DIN) + bq[t]);
        }
        CP_COMMIT();
        #pragma unroll
        for (int t = 0; t < 4; t++) {
            int row = srow[t], kq = skq[t];
            int m = m0 + row;
            float4 xv = make_float4(0.f, 0.f, 0.f, 0.f);
            if (m < nn) xv = *(const float4*)(X + (size_t)m * DIN + kq);
            __nv_bfloat16 h0 = __float2bfloat16_rn(xv.x), h1 = __float2bfloat16_rn(xv.y);
            __nv_bfloat16 h2 = __float2bfloat16_rn(xv.z), h3 = __float2bfloat16_rn(xv.w);
            uint2 hv; hv.x = pack_bf16(h0, h1); hv.y = pack_bf16(h2, h3);
            uint2 lv;
            lv.x = pack_bf16(__float2bfloat16_rn(xv.x - __bfloat162float(h0)),
                             __float2bfloat16_rn(xv.y - __bfloat162float(h1)));
            lv.y = pack_bf16(__float2bfloat16_rn(xv.z - __bfloat162float(h2)),
                             __float2bfloat16_rn(xv.w - __bfloat162float(h3)));
            uint32_t off = swz((uint32_t)(row * 64 + kq * 2));
            *(uint64_t*)(smem + off)          = *(uint64_t*)&hv;
            *(uint64_t*)(smem + TILE_B + off) = *(uint64_t*)&lv;
        }
        CP_WAIT0();
    }
    __syncthreads();

    #pragma unroll 1
    for (int c = 0; c < 16; c++) {
        int s = c & 1;
        float4 areg[4];
        if (c < 15) {
            int koff = (c + 1) * 32;
            uint32_t nst = sm0 + (uint32_t)(s ^ 1) * STAGE_B;
            #pragma unroll
            for (int t = 0; t < 2; t++) {
                uint32_t off = swz((uint32_t)(brow[t] * 64 + bq[t]));
                cp16(nst + 2 * TILE_B + off,
                     (const char*)(g_wth + (size_t)brow[t] * DIN + koff) + bq[t]);
                cp16(nst + 3 * TILE_B + off,
                     (const char*)(g_wtl + (size_t)brow[t] * DIN + koff) + bq[t]);
            }
            CP_COMMIT();
            #pragma unroll
            for (int t = 0; t < 4; t++) {
                int m = m0 + srow[t];
                areg[t] = make_float4(0.f, 0.f, 0.f, 0.f);
                if (m < nn) areg[t] = *(const float4*)(X + (size_t)m * DIN + koff + skq[t]);
            }
        }

        uint32_t stb = sm0 + (uint32_t)s * STAGE_B;
        #pragma unroll
        for (int ks = 0; ks < 2; ks++) {
            uint32_t ahf[2][4], alf[2][4];
            #pragma unroll
            for (int mf = 0; mf < 2; mf++) {
                ldm_x4(ahf[mf], stb + aoff[mf][ks]);
                ldm_x4(alf[mf], stb + TILE_B + aoff[mf][ks]);
            }
            #pragma unroll
            for (int np = 0; np < 4; np++) {
                uint32_t bh4[4], bl4[4];
                ldm_x4(bh4, stb + 2 * TILE_B + boff[np][ks]);
                ldm_x4(bl4, stb + 3 * TILE_B + boff[np][ks]);
                #pragma unroll
                for (int sub = 0; sub < 2; sub++) {
                    int nf = np * 2 + sub;
                    #pragma unroll
                    for (int mf = 0; mf < 2; mf++) {
                        mma16816(d[mf][nf], ahf[mf], bh4 + 2 * sub);
                        mma16816(d[mf][nf], ahf[mf], bl4 + 2 * sub);
                        mma16816(d[mf][nf], alf[mf], bh4 + 2 * sub);
                    }
                }
            }
        }

        if (c < 15) {
            char* st = smem + (size_t)(s ^ 1) * STAGE_B;
            #pragma unroll
            for (int t = 0; t < 4; t++) {
                int row = srow[t], kq = skq[t];
                float4 xv = areg[t];
                __nv_bfloat16 h0 = __float2bfloat16_rn(xv.x), h1 = __float2bfloat16_rn(xv.y);
                __nv_bfloat16 h2 = __float2bfloat16_rn(xv.z), h3 = __float2bfloat16_rn(xv.w);
                uint2 hv; hv.x = pack_bf16(h0, h1); hv.y = pack_bf16(h2, h3);
                uint2 lv;
                lv.x = pack_bf16(__float2bfloat16_rn(xv.x - __bfloat162float(h0)),
                                 __float2bfloat16_rn(xv.y - __bfloat162float(h1)));
                lv.y = pack_bf16(__float2bfloat16_rn(xv.z - __bfloat162float(h2)),
                                 __float2bfloat16_rn(xv.w - __bfloat162float(h3)));
                uint32_t off = swz((uint32_t)(row * 64 + kq * 2));
                *(uint64_t*)(st + off)          = *(uint64_t*)&hv;
                *(uint64_t*)(st + TILE_B + off) = *(uint64_t*)&lv;
            }
        }
        CP_WAIT0();
        __syncthreads();
    }

    // ---- epilogue: write Xp as fp16 ----
    int qrow = lane >> 2;
    #pragma unroll
    for (int mf = 0; mf < 2; mf++) {
        int r0 = m0 + warpm * 32 + mf * 16 + qrow;
        #pragma unroll
        for (int nf = 0; nf < 8; nf++) {
            int col = warpn * 64 + nf * 8 + (lane & 3) * 2;
            if (r0 < nn)
                *(__half2*)(g_xph + (size_t)r0 * DOUT + col) =
                    __floats2half2_rn(d[mf][nf][0], d[mf][nf][1]);
            if (r0 + 8 < nn)
                *(__half2*)(g_xph + (size_t)(r0 + 8) * DOUT + col) =
                    __floats2half2_rn(d[mf][nf][2], d[mf][nf][3]);
        }
    }
}

// ---------------- CSR build --------------------------------------------------
__global__ void k_hist(const int* __restrict__ rows, int ne) {
    int i = blockIdx.x * blockDim.x + threadIdx.x;
    int b = i * 4;
    if (b + 3 < ne) {
        int4 r = *(const int4*)(rows + b);
        atomicAdd(&g_deg[r.x], 1);
        atomicAdd(&g_deg[r.y], 1);
        atomicAdd(&g_deg[r.z], 1);
        atomicAdd(&g_deg[r.w], 1);
    } else {
        for (int e = b; e < ne; e++) atomicAdd(&g_deg[rows[e]], 1);
    }
}

// row-base allocation: warp-aggregated atomic; seeds cursor with the base
__global__ void k_alloc(int n) {
    int i = blockIdx.x * blockDim.x + threadIdx.x;
    int lane = threadIdx.x & 31;
    int d = (i < n) ? g_deg[i] : 0;
    int incl = d;
    #pragma unroll
    for (int o = 1; o < 32; o <<= 1) {
        int v = __shfl_up_sync(0xffffffffu, incl, o);
        if (lane >= o) incl += v;
    }
    int wsum = __shfl_sync(0xffffffffu, incl, 31);
    int base = 0;
    if (lane == 31 && wsum > 0) base = atomicAdd(&g_total, wsum);
    base = __shfl_sync(0xffffffffu, base, 31);
    if (i < n) {
        int rp = base + incl - d;
        g_rowptr[i] = rp;
        g_cursor[i] = rp;
    }
}

__global__ void k_scatter(const int* __restrict__ rows, const int* __restrict__ cols,
                          const float* __restrict__ vals, int ne) {
    int i = blockIdx.x * blockDim.x + threadIdx.x;
    int b = i * 4;
    if (b + 3 < ne) {
        int4   r = *(const int4*)(rows + b);
        int4   c = *(const int4*)(cols + b);
        float4 v = *(const float4*)(vals + b);
        int p0 = atomicAdd(&g_cursor[r.x], 1);
        g_edge[p0] = make_int2(c.x, __float_as_int(v.x));
        int p1 = atomicAdd(&g_cursor[r.y], 1);
        g_edge[p1] = make_int2(c.y, __float_as_int(v.y));
        int p2 = atomicAdd(&g_cursor[r.z], 1);
        g_edge[p2] = make_int2(c.z, __float_as_int(v.z));
        int p3 = atomicAdd(&g_cursor[r.w], 1);
        g_edge[p3] = make_int2(c.w, __float_as_int(v.w));
    } else {
        for (int e = b; e < ne; e++) {
            int pos = atomicAdd(&g_cursor[rows[e]], 1);
            g_edge[pos] = make_int2(cols[e], __float_as_int(vals[e]));
        }
    }
}

// ---------------- SpMM + tanh: warp per row, fp16 gathers, MLP=4 ------------
__global__ void __launch_bounds__(256) k_spmm(float* __restrict__ out, int n) {
    int warp = (blockIdx.x * blockDim.x + threadIdx.x) >> 5;
    int lane = threadIdx.x & 31;
    if (warp >= n) return;
    int beg = g_rowptr[warp];
    int end = beg + g_deg[warp];
    const __half* xpb = g_xph + lane * 4;
    float4 acc = make_float4(0.f, 0.f, 0.f, 0.f);
    for (int b = beg; b < end; b += 32) {
        int idx = b + lane;
        int cc = 0; float vv = 0.f;
        if (idx < end) {
            int2 e = __ldg(&g_edge[idx]);
            cc = e.x; vv = __int_as_float(e.y);
        }
        int cnt = min(32, end - b);
        int cnt4 = (cnt + 3) & ~3;
        for (int j = 0; j < cnt4; j += 4) {
            int   c0 = __shfl_sync(0xffffffffu, cc, j);
            int   c1 = __shfl_sync(0xffffffffu, cc, j + 1);
            int   c2 = __shfl_sync(0xffffffffu, cc, j + 2);
            int   c3 = __shfl_sync(0xffffffffu, cc, j + 3);
            float v0 = __shfl_sync(0xffffffffu, vv, j);
            float v1 = __shfl_sync(0xffffffffu, vv, j + 1);
            float v2 = __shfl_sync(0xffffffffu, vv, j + 2);
            float v3 = __shfl_sync(0xffffffffu, vv, j + 3);
            uint2 h0 = __ldg((const uint2*)(xpb + (size_t)c0 * DOUT));
            uint2 h1 = __ldg((const uint2*)(xpb + (size_t)c1 * DOUT));
            uint2 h2 = __ldg((const uint2*)(xpb + (size_t)c2 * DOUT));
            uint2 h3 = __ldg((const uint2*)(xpb + (size_t)c3 * DOUT));
            float2 a0 = __half22float2(*(__half2*)&h0.x), b0 = __half22float2(*(__half2*)&h0.y);
            float2 a1 = __half22float2(*(__half2*)&h1.x), b1 = __half22float2(*(__half2*)&h1.y);
            float2 a2 = __half22float2(*(__half2*)&h2.x), b2 = __half22float2(*(__half2*)&h2.y);
            float2 a3 = __half22float2(*(__half2*)&h3.x), b3 = __half22float2(*(__half2*)&h3.y);
            acc.x = fmaf(v0, a0.x, acc.x); acc.y = fmaf(v0, a0.y, acc.y);
            acc.z = fmaf(v0, b0.x, acc.z); acc.w = fmaf(v0, b0.y, acc.w);
            acc.x = fmaf(v1, a1.x, acc.x); acc.y = fmaf(v1, a1.y, acc.y);
            acc.z = fmaf(v1, b1.x, acc.z); acc.w = fmaf(v1, b1.y, acc.w);
            acc.x = fmaf(v2, a2.x, acc.x); acc.y = fmaf(v2, a2.y, acc.y);
            acc.z = fmaf(v2, b2.x, acc.z); acc.w = fmaf(v2, b2.y, acc.w);
            acc.x = fmaf(v3, a3.x, acc.x); acc.y = fmaf(v3, a3.y, acc.y);
            acc.z = fmaf(v3, b3.x, acc.z); acc.w = fmaf(v3, b3.y, acc.w);
        }
    }
    float4 o;
    o.x = tanhf(acc.x); o.y = tanhf(acc.y);
    o.z = tanhf(acc.z); o.w = tanhf(acc.w);
    *(float4*)(out + (size_t)warp * DOUT + lane * 4) = o;
}

// ---------------- launch (single stream) -------------------------------------
extern "C" void kernel_launch(void* const* d_in, const int* in_sizes, int n_in,
                              void* d_out, int out_size) {
    const float* X    = (const float*)d_in[0];   // [N, 512]
    const float* W    = (const float*)d_in[1];   // [512, 128]
    const float* vals = (const float*)d_in[2];   // [E]
    const int*   rows = (const int*)d_in[3];     // [E]
    const int*   cols = (const int*)d_in[4];     // [E]
    float* out = (float*)d_out;

    int nn = in_sizes[0] / DIN;
    int ne = in_sizes[2];

    cudaFuncSetAttribute(k_cholinv, cudaFuncAttributeMaxDynamicSharedMemorySize, CI_SMEM);
    cudaFuncSetAttribute(k_wortho,  cudaFuncAttributeMaxDynamicSharedMemorySize, WO_SMEM);
    cudaFuncSetAttribute(k_gemm,    cudaFuncAttributeMaxDynamicSharedMemorySize, GEMM_SMEM);

    int zblocks = (nn + 127) / 128;
    int e4 = (ne + 3) / 4;

    // ncu lands on launch index 3 -> k_gemm profiled
    kA<<<DOUT + zblocks, 128>>>(W, nn);                          // 0
    k_cholinv<<<1, 512, CI_SMEM>>>();                            // 1
    k_wortho<<<16, 256, WO_SMEM>>>(W);                           // 2
    k_gemm<<<(nn + 127) / 128, 256, GEMM_SMEM>>>(X, nn);         // 3  <- profiled
    k_hist<<<(e4 + 255) / 256, 256>>>(rows, ne);                 // 4
    k_alloc<<<(nn + 255) / 256, 256>>>(nn);                      // 5
    k_scatter<<<(e4 + 255) / 256, 256>>>(rows, cols, vals, ne);  // 6
    k_spmm<<<(nn * 32 + 255) / 256, 256>>>(out, nn);             // 7
}

// round 15
// speedup vs baseline: 1.0284x; 1.0284x over previous
#include <cuda_runtime.h>
#include <cuda_bf16.h>
#include <cuda_fp16.h>
#include <cstdint>
#include <cstring>
#include <math.h>

#define DIN  512
#define DOUT 128
#define MAXN 100000
#define MAXE 3200000

// ---------------- device-global scratch (no runtime allocation) ------------
__device__ __align__(16) __half g_xph[(size_t)MAXN * DOUT];    // projected X, fp16
__device__ __align__(16) float g_G[DOUT * DOUT];               // gram -> chol L
__device__ __align__(16) float g_Minv[DOUT * DOUT];            // inv(L), upper=0
__device__ __align__(16) __nv_bfloat16 g_wth[DOUT * DIN];      // W_ortho^T hi  [n][k]
__device__ __align__(16) __nv_bfloat16 g_wtl[DOUT * DIN];      // W_ortho^T lo  [n][k]
__device__ int   g_deg[MAXN];
__device__ int   g_rowptr[MAXN];
__device__ int   g_cursor[MAXN];
__device__ int   g_total;
__device__ __align__(8) int2 g_edge[MAXE];                     // .x=col .y=val bits

__device__ __forceinline__ uint32_t pack_bf16(__nv_bfloat16 a, __nv_bfloat16 b) {
    __nv_bfloat162 t(a, b);
    uint32_t r; memcpy(&r, &t, 4); return r;
}

__device__ __forceinline__ uint32_t smem_u32(const void* p) {
    return (uint32_t)__cvta_generic_to_shared(p);
}

// async 16B copy, L1-bypass
__device__ __forceinline__ void cp16(uint32_t s, const void* g) {
    asm volatile("cp.async.cg.shared.global [%0], [%1], 16;" :: "r"(s), "l"(g));
}
#define CP_COMMIT() asm volatile("cp.async.commit_group;")
#define CP_WAIT0()  asm volatile("cp.async.wait_group 0;")

// warp-level bf16 MMA (sm_80+; compiles on plain sm_100 target)
__device__ __forceinline__ void mma16816(float* d, const uint32_t* a, const uint32_t* b) {
    asm volatile("mma.sync.aligned.m16n8k16.row.col.f32.bf16.bf16.f32 "
        "{%0,%1,%2,%3}, {%4,%5,%6,%7}, {%8,%9}, {%0,%1,%2,%3};"
        : "+f"(d[0]), "+f"(d[1]), "+f"(d[2]), "+f"(d[3])
        : "r"(a[0]), "r"(a[1]), "r"(a[2]), "r"(a[3]), "r"(b[0]), "r"(b[1]));
}

__device__ __forceinline__ void ldm_x4(uint32_t* r, uint32_t addr) {
    asm volatile("ldmatrix.sync.aligned.m8n8.x4.shared.b16 {%0,%1,%2,%3}, [%4];"
        : "=r"(r[0]), "=r"(r[1]), "=r"(r[2]), "=r"(r[3]) : "r"(addr));
}

// XOR swizzle on 64B rows packed in 128B lines: bits[4:6] ^= bits[7:9]
__device__ __forceinline__ uint32_t swz(uint32_t off) {
    return off ^ ((off >> 3) & 0x70);
}

// ---------------- kA: Gram matrix + zero deg/total ---------------------------
__global__ void __launch_bounds__(128) kA(const float* __restrict__ W, int n) {
    if (blockIdx.x < DOUT) {
        __shared__ float col[DIN];
        int i = blockIdx.x, j = threadIdx.x;
        for (int k = j; k < DIN; k += DOUT) col[k] = W[k * DOUT + i];
        __syncthreads();
        float acc = 0.f;
        #pragma unroll 8
        for (int k = 0; k < DIN; k++) acc = fmaf(col[k], W[k * DOUT + j], acc);
        g_G[i * DOUT + j] = acc + (i == j ? 1e-4f : 0.f);
    } else {
        if (blockIdx.x == DOUT && threadIdx.x == 0) g_total = 0;
        int i = (blockIdx.x - DOUT) * 128 + threadIdx.x;
        if (i < n) g_deg[i] = 0;
    }
}

// ---------------- Cholesky: 512 threads, 4 per row, pitch-129 smem ----------
static constexpr int CP_ = 129;
static constexpr int CHOL_SMEM = (DOUT * CP_ + DOUT) * 4;   // 66560 B

__global__ void __launch_bounds__(512) k_chol() {
    extern __shared__ float s[];
    float* diag = s + DOUT * CP_;
    int tid = threadIdx.x;
    int t = tid >> 2;        // row 0..127
    int q = tid & 3;         // column-quarter within row
    for (int idx = tid; idx < DOUT * DOUT; idx += 512) {
        int r = idx >> 7, c = idx & 127;
        s[r * CP_ + c] = g_G[idx];
    }
    __syncthreads();
    for (int k = 0; k < DOUT; k++) {
        float dk = sqrtf(s[k * CP_ + k]);
        if (tid == 0) diag[k] = dk;
        if (q == 0 && t > k) s[t * CP_ + k] /= dk;
        __syncthreads();
        if (t > k) {
            float lik = s[t * CP_ + k];
            for (int j = k + 1 + q; j <= t; j += 4)
                s[t * CP_ + j] -= lik * s[j * CP_ + k];
        }
        __syncthreads();
    }
    for (int idx = tid; idx < DOUT * DOUT; idx += 512) {
        int r = idx >> 7, c = idx & 127;
        g_G[idx] = (r == c) ? diag[r] : s[r * CP_ + c];
    }
}

// ---------------- inv(L): one warp per column, 8 blocks x 512 ---------------
// Column j solves L m = e_j. Lanes split each row-sum, shfl-reduced; serial
// depth 128 but 128 independent warps hide each other's latency.
static constexpr int LINV_SMEM = (DOUT * CP_ + 16 * DOUT) * 4;  // 74240 B

__global__ void __launch_bounds__(512) k_linv() {
    extern __shared__ float s[];
    float* Ls = s;                       // 128 x pitch129 (L, true diag)
    float* mc = s + DOUT * CP_;          // 16 warps x 128
    int tid = threadIdx.x;
    int wid = tid >> 5, lane = tid & 31;
    for (int idx = tid; idx < DOUT * DOUT; idx += 512) {
        int r = idx >> 7, c = idx & 127;
        Ls[r * CP_ + c] = g_G[idx];
    }
    __syncthreads();

    int j = blockIdx.x * 16 + wid;       // this warp's column
    float* m = mc + wid * DOUT;
    if (lane == 0) m[j] = 1.f / Ls[j * CP_ + j];
    __syncwarp();
    for (int i = j + 1; i < DOUT; i++) {
        float p = 0.f;
        for (int k = j + lane; k < i; k += 32)
            p = fmaf(Ls[i * CP_ + k], m[k], p);
        #pragma unroll
        for (int o = 16; o; o >>= 1) p += __shfl_xor_sync(0xffffffffu, p, o);
        if (lane == 0) m[i] = -p / Ls[i * CP_ + i];
        __syncwarp();
    }
    for (int i = lane; i < DOUT; i += 32)
        g_Minv[i * DOUT + j] = (i >= j) ? m[i] : 0.f;
}

// ---------------- W_ortho = W @ inv(L)^T  (free-order, 16 blocks) -----------
// W_ortho[r][j] = sum_{k<=j} W[r][k] * M[j][k];  emit bf16 hi/lo at [n=j][k=r].
static constexpr int WP_ = 132;                       // W smem pitch (floats)
static constexpr int WO_SMEM = (DOUT * CP_ + 32 * WP_) * 4;   // 82944 B

__global__ void __launch_bounds__(256) k_wortho(const float* __restrict__ W) {
    extern __shared__ float s[];
    float* Ms = s;                  // 128 x pitch129 (inv(L))
    float* Ws = s + DOUT * CP_;     // 32 rows x pitch132
    int tid = threadIdx.x;
    int r0 = blockIdx.x * 32;

    for (int idx = tid; idx < DOUT * DOUT; idx += 256) {
        int r = idx >> 7, c = idx & 127;
        Ms[r * CP_ + c] = g_Minv[idx];
    }
    for (int idx = tid; idx < 32 * DOUT; idx += 256) {
        int rl = idx >> 7, c = idx & 127;
        Ws[rl * WP_ + c] = W[(size_t)(r0 + rl) * DOUT + c];
    }
    __syncthreads();

    int rl = tid >> 3;              // 0..31 local row
    int jq = tid & 7;               // j = jq + 8*jj  (conflict-free across warp)
    int r = r0 + rl;
    const float* wrow = Ws + rl * WP_;
    for (int jj = 0; jj < 16; jj++) {
        int j = jq + 8 * jj;
        const float* mrow = Ms + j * CP_;
        float s0 = 0.f, s1 = 0.f, s2 = 0.f, s3 = 0.f;
        int k = 0;
        for (; k + 3 <= j; k += 4) {
            s0 = fmaf(wrow[k],     mrow[k],     s0);
            s1 = fmaf(wrow[k + 1], mrow[k + 1], s1);
            s2 = fmaf(wrow[k + 2], mrow[k + 2], s2);
            s3 = fmaf(wrow[k + 3], mrow[k + 3], s3);
        }
        for (; k <= j; k++) s0 = fmaf(wrow[k], mrow[k], s0);
        float sv = (s0 + s1) + (s2 + s3);
        __nv_bfloat16 h = __float2bfloat16_rn(sv);
        g_wth[j * DIN + r] = h;
        g_wtl[j * DIN + r] = __float2bfloat16_rn(sv - __bfloat162float(h));
    }
}

// ---------------- GEMM: Xp = X @ W_ortho  (mma.sync bf16 hi/lo split) -------
static constexpr int TILE_B  = 128 * 64;            // 8192
static constexpr int STAGE_B = 4 * TILE_B;          // 32768 (Ah, Al, Bh, Bl)
static constexpr int GEMM_SMEM = 2 * STAGE_B;       // 65536

__global__ void __launch_bounds__(256, 2)
k_gemm(const float* __restrict__ X, int nn) {
    extern __shared__ char smem[];
    uint32_t sm0 = smem_u32(smem);
    int tid  = threadIdx.x;
    int lane = tid & 31;
    int wid  = tid >> 5;
    int warpm = wid & 3;
    int warpn = wid >> 2;
    int m0 = blockIdx.x * 128;

    float d[2][8][4];
    #pragma unroll
    for (int mf = 0; mf < 2; mf++)
        #pragma unroll
        for (int nf = 0; nf < 8; nf++)
            #pragma unroll
            for (int q = 0; q < 4; q++) d[mf][nf][q] = 0.f;

    int srow[4], skq[4];
    #pragma unroll
    for (int t = 0; t < 4; t++) {
        int idx = tid + t * 256;
        srow[t] = idx >> 3;
        skq[t]  = (idx & 7) << 2;
    }
    int brow[2], bq[2];
    #pragma unroll
    for (int t = 0; t < 2; t++) {
        int idx = tid + t * 256;
        brow[t] = idx >> 2;
        bq[t]   = (idx & 3) * 16;
    }

    uint32_t aoff[2][2];
    {
        int arow = warpm * 32 + ((lane >> 3) & 1) * 8 + (lane & 7);
        int akb  = (lane >> 4) << 4;
        #pragma unroll
        for (int mf = 0; mf < 2; mf++)
            #pragma unroll
            for (int ks = 0; ks < 2; ks++)
                aoff[mf][ks] = swz((uint32_t)((arow + mf * 16) * 64 + ks * 32 + akb));
    }
    uint32_t boff[4][2];
    {
        int bn  = warpn * 64 + ((lane >= 16) ? 8 : 0) + (lane & 7);
        int bkb = ((lane >> 3) & 1) * 16;
        #pragma unroll
        for (int np = 0; np < 4; np++)
            #pragma unroll
            for (int ks = 0; ks < 2; ks++)
                boff[np][ks] = swz((uint32_t)((bn + np * 16) * 64 + ks * 32 + bkb));
    }

    // ---- prologue: chunk 0 ----
    {
        uint32_t sBh = sm0 + 2 * TILE_B, sBl = sm0 + 3 * TILE_B;
        #pragma unroll
        for (int t = 0; t < 2; t++) {
            uint32_t off = swz((uint32_t)(brow[t] * 64 + bq[t]));
            cp16(sBh + off, (const char*)(g_wth + (size_t)brow[t] * DIN) + bq[t]);
            cp16(sBl + off, (const char*)(g_wtl + (size_t)brow[t] * DIN) + bq[t]);
        }
        CP_COMMIT();
        #pragma unroll
        for (int t = 0; t < 4; t++) {
            int row = srow[t], kq = skq[t];
            int m = m0 + row;
            float4 xv = make_float4(0.f, 0.f, 0.f, 0.f);
            if (m < nn) xv = *(const float4*)(X + (size_t)m * DIN + kq);
            __nv_bfloat16 h0 = __float2bfloat16_rn(xv.x), h1 = __float2bfloat16_rn(xv.y);
            __nv_bfloat16 h2 = __float2bfloat16_rn(xv.z), h3 = __float2bfloat16_rn(xv.w);
            uint2 hv; hv.x = pack_bf16(h0, h1); hv.y = pack_bf16(h2, h3);
            uint2 lv;
            lv.x = pack_bf16(__float2bfloat16_rn(xv.x - __bfloat162float(h0)),
                             __float2bfloat16_rn(xv.y - __bfloat162float(h1)));
            lv.y = pack_bf16(__float2bfloat16_rn(xv.z - __bfloat162float(h2)),
                             __float2bfloat16_rn(xv.w - __bfloat162float(h3)));
            uint32_t off = swz((uint32_t)(row * 64 + kq * 2));
            *(uint64_t*)(smem + off)          = *(uint64_t*)&hv;
            *(uint64_t*)(smem + TILE_B + off) = *(uint64_t*)&lv;
        }
        CP_WAIT0();
    }
    __syncthreads();

    #pragma unroll 1
    for (int c = 0; c < 16; c++) {
        int s = c & 1;
        float4 areg[4];
        if (c < 15) {
            int koff = (c + 1) * 32;
            uint32_t nst = sm0 + (uint32_t)(s ^ 1) * STAGE_B;
            #pragma unroll
            for (int t = 0; t < 2; t++) {
                uint32_t off = swz((uint32_t)(brow[t] * 64 + bq[t]));
                cp16(nst + 2 * TILE_B + off,
                     (const char*)(g_wth + (size_t)brow[t] * DIN + koff) + bq[t]);
                cp16(nst + 3 * TILE_B + off,
                     (const char*)(g_wtl + (size_t)brow[t] * DIN + koff) + bq[t]);
            }
            CP_COMMIT();
            #pragma unroll
            for (int t = 0; t < 4; t++) {
                int m = m0 + srow[t];
                areg[t] = make_float4(0.f, 0.f, 0.f, 0.f);
                if (m < nn) areg[t] = *(const float4*)(X + (size_t)m * DIN + koff + skq[t]);
            }
        }

        uint32_t stb = sm0 + (uint32_t)s * STAGE_B;
        #pragma unroll
        for (int ks = 0; ks < 2; ks++) {
            uint32_t ahf[2][4], alf[2][4];
            #pragma unroll
            for (int mf = 0; mf < 2; mf++) {
                ldm_x4(ahf[mf], stb + aoff[mf][ks]);
                ldm_x4(alf[mf], stb + TILE_B + aoff[mf][ks]);
            }
            #pragma unroll
            for (int np = 0; np < 4; np++) {
                uint32_t bh4[4], bl4[4];
                ldm_x4(bh4, stb + 2 * TILE_B + boff[np][ks]);
                ldm_x4(bl4, stb + 3 * TILE_B + boff[np][ks]);
                #pragma unroll
                for (int sub = 0; sub < 2; sub++) {
                    int nf = np * 2 + sub;
                    #pragma unroll
                    for (int mf = 0; mf < 2; mf++) {
                        mma16816(d[mf][nf], ahf[mf], bh4 + 2 * sub);
                        mma16816(d[mf][nf], ahf[mf], bl4 + 2 * sub);
                        mma16816(d[mf][nf], alf[mf], bh4 + 2 * sub);
                    }
                }
            }
        }

        if (c < 15) {
            char* st = smem + (size_t)(s ^ 1) * STAGE_B;
            #pragma unroll
            for (int t = 0; t < 4; t++) {
                int row = srow[t], kq = skq[t];
                float4 xv = areg[t];
                __nv_bfloat16 h0 = __float2bfloat16_rn(xv.x), h1 = __float2bfloat16_rn(xv.y);
                __nv_bfloat16 h2 = __float2bfloat16_rn(xv.z), h3 = __float2bfloat16_rn(xv.w);
                uint2 hv; hv.x = pack_bf16(h0, h1); hv.y = pack_bf16(h2, h3);
                uint2 lv;
                lv.x = pack_bf16(__float2bfloat16_rn(xv.x - __bfloat162float(h0)),
                                 __float2bfloat16_rn(xv.y - __bfloat162float(h1)));
                lv.y = pack_bf16(__float2bfloat16_rn(xv.z - __bfloat162float(h2)),
                                 __float2bfloat16_rn(xv.w - __bfloat162float(h3)));
                uint32_t off = swz((uint32_t)(row * 64 + kq * 2));
                *(uint64_t*)(st + off)          = *(uint64_t*)&hv;
                *(uint64_t*)(st + TILE_B + off) = *(uint64_t*)&lv;
            }
        }
        CP_WAIT0();
        __syncthreads();
    }

    // ---- epilogue: write Xp as fp16 ----
    int qrow = lane >> 2;
    #pragma unroll
    for (int mf = 0; mf < 2; mf++) {
        int r0 = m0 + warpm * 32 + mf * 16 + qrow;
        #pragma unroll
        for (int nf = 0; nf < 8; nf++) {
            int col = warpn * 64 + nf * 8 + (lane & 3) * 2;
            if (r0 < nn)
                *(__half2*)(g_xph + (size_t)r0 * DOUT + col) =
                    __floats2half2_rn(d[mf][nf][0], d[mf][nf][1]);
            if (r0 + 8 < nn)
                *(__half2*)(g_xph + (size_t)(r0 + 8) * DOUT + col) =
                    __floats2half2_rn(d[mf][nf][2], d[mf][nf][3]);
        }
    }
}

// ---------------- CSR build --------------------------------------------------
__global__ void k_hist(const int* __restrict__ rows, int ne) {
    int i = blockIdx.x * blockDim.x + threadIdx.x;
    int b = i * 4;
    if (b + 3 < ne) {
        int4 r = *(const int4*)(rows + b);
        atomicAdd(&g_deg[r.x], 1);
        atomicAdd(&g_deg[r.y], 1);
        atomicAdd(&g_deg[r.z], 1);
        atomicAdd(&g_deg[r.w], 1);
    } else {
        for (int e = b; e < ne; e++) atomicAdd(&g_deg[rows[e]], 1);
    }
}

// row-base allocation: warp-aggregated atomic; seeds cursor with the base
__global__ void k_alloc(int n) {
    int i = blockIdx.x * blockDim.x + threadIdx.x;
    int lane = threadIdx.x & 31;
    int d = (i < n) ? g_deg[i] : 0;
    int incl = d;
    #pragma unroll
    for (int o = 1; o < 32; o <<= 1) {
        int v = __shfl_up_sync(0xffffffffu, incl, o);
        if (lane >= o) incl += v;
    }
    int wsum = __shfl_sync(0xffffffffu, incl, 31);
    int base = 0;
    if (lane == 31 && wsum > 0) base = atomicAdd(&g_total, wsum);
    base = __shfl_sync(0xffffffffu, base, 31);
    if (i < n) {
        int rp = base + incl - d;
        g_rowptr[i] = rp;
        g_cursor[i] = rp;
    }
}

__global__ void k_scatter(const int* __restrict__ rows, const int* __restrict__ cols,
                          const float* __restrict__ vals, int ne) {
    int i = blockIdx.x * blockDim.x + threadIdx.x;
    int b = i * 4;
    if (b + 3 < ne) {
        int4   r = *(const int4*)(rows + b);
        int4   c = *(const int4*)(cols + b);
        float4 v = *(const float4*)(vals + b);
        int p0 = atomicAdd(&g_cursor[r.x], 1);
        g_edge[p0] = make_int2(c.x, __float_as_int(v.x));
        int p1 = atomicAdd(&g_cursor[r.y], 1);
        g_edge[p1] = make_int2(c.y, __float_as_int(v.y));
        int p2 = atomicAdd(&g_cursor[r.z], 1);
        g_edge[p2] = make_int2(c.z, __float_as_int(v.z));
        int p3 = atomicAdd(&g_cursor[r.w], 1);
        g_edge[p3] = make_int2(c.w, __float_as_int(v.w));
    } else {
        for (int e = b; e < ne; e++) {
            int pos = atomicAdd(&g_cursor[rows[e]], 1);
            g_edge[pos] = make_int2(cols[e], __float_as_int(vals[e]));
        }
    }
}

// ---------------- SpMM + tanh: warp per row, fp16 gathers, MLP=4 ------------
__global__ void __launch_bounds__(256) k_spmm(float* __restrict__ out, int n) {
    int warp = (blockIdx.x * blockDim.x + threadIdx.x) >> 5;
    int lane = threadIdx.x & 31;
    if (warp >= n) return;
    int beg = g_rowptr[warp];
    int end = beg + g_deg[warp];
    const __half* xpb = g_xph + lane * 4;
    float4 acc = make_float4(0.f, 0.f, 0.f, 0.f);
    for (int b = beg; b < end; b += 32) {
        int idx = b + lane;
        int cc = 0; float vv = 0.f;
        if (idx < end) {
            int2 e = __ldg(&g_edge[idx]);
            cc = e.x; vv = __int_as_float(e.y);
        }
        int cnt = min(32, end - b);
        int cnt4 = (cnt + 3) & ~3;
        for (int j = 0; j < cnt4; j += 4) {
            int   c0 = __shfl_sync(0xffffffffu, cc, j);
            int   c1 = __shfl_sync(0xffffffffu, cc, j + 1);
            int   c2 = __shfl_sync(0xffffffffu, cc, j + 2);
            int   c3 = __shfl_sync(0xffffffffu, cc, j + 3);
            float v0 = __shfl_sync(0xffffffffu, vv, j);
            float v1 = __shfl_sync(0xffffffffu, vv, j + 1);
            float v2 = __shfl_sync(0xffffffffu, vv, j + 2);
            float v3 = __shfl_sync(0xffffffffu, vv, j + 3);
            uint2 h0 = __ldg((const uint2*)(xpb + (size_t)c0 * DOUT));
            uint2 h1 = __ldg((const uint2*)(xpb + (size_t)c1 * DOUT));
            uint2 h2 = __ldg((const uint2*)(xpb + (size_t)c2 * DOUT));
            uint2 h3 = __ldg((const uint2*)(xpb + (size_t)c3 * DOUT));
            float2 a0 = __half22float2(*(__half2*)&h0.x), b0 = __half22float2(*(__half2*)&h0.y);
            float2 a1 = __half22float2(*(__half2*)&h1.x), b1 = __half22float2(*(__half2*)&h1.y);
            float2 a2 = __half22float2(*(__half2*)&h2.x), b2 = __half22float2(*(__half2*)&h2.y);
            float2 a3 = __half22float2(*(__half2*)&h3.x), b3 = __half22float2(*(__half2*)&h3.y);
            acc.x = fmaf(v0, a0.x, acc.x); acc.y = fmaf(v0, a0.y, acc.y);
            acc.z = fmaf(v0, b0.x, acc.z); acc.w = fmaf(v0, b0.y, acc.w);
            acc.x = fmaf(v1, a1.x, acc.x); acc.y = fmaf(v1, a1.y, acc.y);
            acc.z = fmaf(v1, b1.x, acc.z); acc.w = fmaf(v1, b1.y, acc.w);
            acc.x = fmaf(v2, a2.x, acc.x); acc.y = fmaf(v2, a2.y, acc.y);
            acc.z = fmaf(v2, b2.x, acc.z); acc.w = fmaf(v2, b2.y, acc.w);
            acc.x = fmaf(v3, a3.x, acc.x); acc.y = fmaf(v3, a3.y, acc.y);
            acc.z = fmaf(v3, b3.x, acc.z); acc.w = fmaf(v3, b3.y, acc.w);
        }
    }
    float4 o;
    o.x = tanhf(acc.x); o.y = tanhf(acc.y);
    o.z = tanhf(acc.z); o.w = tanhf(acc.w);
    *(float4*)(out + (size_t)warp * DOUT + lane * 4) = o;
}

// ---------------- launch (single stream) -------------------------------------
extern "C" void kernel_launch(void* const* d_in, const int* in_sizes, int n_in,
                              void* d_out, int out_size) {
    const float* X    = (const float*)d_in[0];   // [N, 512]
    const float* W    = (const float*)d_in[1];   // [512, 128]
    const float* vals = (const float*)d_in[2];   // [E]
    const int*   rows = (const int*)d_in[3];     // [E]
    const int*   cols = (const int*)d_in[4];     // [E]
    float* out = (float*)d_out;

    int nn = in_sizes[0] / DIN;
    int ne = in_sizes[2];

    cudaFuncSetAttribute(k_chol,   cudaFuncAttributeMaxDynamicSharedMemorySize, CHOL_SMEM);
    cudaFuncSetAttribute(k_linv,   cudaFuncAttributeMaxDynamicSharedMemorySize, LINV_SMEM);
    cudaFuncSetAttribute(k_wortho, cudaFuncAttributeMaxDynamicSharedMemorySize, WO_SMEM);
    cudaFuncSetAttribute(k_gemm,   cudaFuncAttributeMaxDynamicSharedMemorySize, GEMM_SMEM);

    int zblocks = (nn + 127) / 128;
    int e4 = (ne + 3) / 4;

    // ncu lands on launch index 3 -> k_linv profiled (new kernel, verify it)
    kA<<<DOUT + zblocks, 128>>>(W, nn);                          // 0
    k_chol<<<1, 512, CHOL_SMEM>>>();                             // 1
    k_hist<<<(e4 + 255) / 256, 256>>>(rows, ne);                 // 2
    k_linv<<<8, 512, LINV_SMEM>>>();                             // 3  <- profiled
    k_wortho<<<16, 256, WO_SMEM>>>(W);                           // 4
    k_alloc<<<(nn + 255) / 256, 256>>>(nn);                      // 5
    k_gemm<<<(nn + 127) / 128, 256, GEMM_SMEM>>>(X, nn);         // 6
    k_scatter<<<(e4 + 255) / 256, 256>>>(rows, cols, vals, ne);  // 7
    k_spmm<<<(nn * 32 + 255) / 256, 256>>>(out, nn);             // 8
}

// round 16
// speedup vs baseline: 1.0889x; 1.0587x over previous
#include <cuda_runtime.h>
#include <cuda_bf16.h>
#include <cuda_fp16.h>
#include <cstdint>
#include <cstring>
#include <math.h>

#define DIN  512
#define DOUT 128
#define MAXN 100000
#define MAXE 3200000

// ---------------- device-global scratch (no runtime allocation) ------------
__device__ __align__(16) __half g_xph[(size_t)MAXN * DOUT];    // projected X, fp16
__device__ __align__(16) float g_G[DOUT * DOUT];               // gram -> chol L
__device__ __align__(16) float g_Minv[DOUT * DOUT];            // inv(L), upper=0
__device__ __align__(16) __nv_bfloat16 g_wth[DOUT * DIN];      // W_ortho^T hi  [n][k]
__device__ __align__(16) __nv_bfloat16 g_wtl[DOUT * DIN];      // W_ortho^T lo  [n][k]
__device__ int   g_deg[MAXN];
__device__ int   g_rowptr[MAXN];
__device__ int   g_cursor[MAXN];
__device__ int   g_total;
__device__ __align__(8) int2 g_edge[MAXE];                     // .x=col .y=val bits

__device__ __forceinline__ uint32_t pack_bf16(__nv_bfloat16 a, __nv_bfloat16 b) {
    __nv_bfloat162 t(a, b);
    uint32_t r; memcpy(&r, &t, 4); return r;
}

__device__ __forceinline__ uint32_t smem_u32(const void* p) {
    return (uint32_t)__cvta_generic_to_shared(p);
}

// async 16B copy, L1-bypass
__device__ __forceinline__ void cp16(uint32_t s, const void* g) {
    asm volatile("cp.async.cg.shared.global [%0], [%1], 16;" :: "r"(s), "l"(g));
}
#define CP_COMMIT() asm volatile("cp.async.commit_group;")
#define CP_WAIT0()  asm volatile("cp.async.wait_group 0;")

// warp-level bf16 MMA (sm_80+; compiles on plain sm_100 target)
__device__ __forceinline__ void mma16816(float* d, const uint32_t* a, const uint32_t* b) {
    asm volatile("mma.sync.aligned.m16n8k16.row.col.f32.bf16.bf16.f32 "
        "{%0,%1,%2,%3}, {%4,%5,%6,%7}, {%8,%9}, {%0,%1,%2,%3};"
        : "+f"(d[0]), "+f"(d[1]), "+f"(d[2]), "+f"(d[3])
        : "r"(a[0]), "r"(a[1]), "r"(a[2]), "r"(a[3]), "r"(b[0]), "r"(b[1]));
}

__device__ __forceinline__ void ldm_x4(uint32_t* r, uint32_t addr) {
    asm volatile("ldmatrix.sync.aligned.m8n8.x4.shared.b16 {%0,%1,%2,%3}, [%4];"
        : "=r"(r[0]), "=r"(r[1]), "=r"(r[2]), "=r"(r[3]) : "r"(addr));
}

// XOR swizzle on 64B rows packed in 128B lines: bits[4:6] ^= bits[7:9]
__device__ __forceinline__ uint32_t swz(uint32_t off) {
    return off ^ ((off >> 3) & 0x70);
}

// ---------------- kA: Gram matrix + zero deg/total ---------------------------
__global__ void __launch_bounds__(128) kA(const float* __restrict__ W, int n) {
    if (blockIdx.x < DOUT) {
        __shared__ float col[DIN];
        int i = blockIdx.x, j = threadIdx.x;
        for (int k = j; k < DIN; k += DOUT) col[k] = W[k * DOUT + i];
        __syncthreads();
        float acc = 0.f;
        #pragma unroll 8
        for (int k = 0; k < DIN; k++) acc = fmaf(col[k], W[k * DOUT + j], acc);
        g_G[i * DOUT + j] = acc + (i == j ? 1e-4f : 0.f);
    } else {
        if (blockIdx.x == DOUT && threadIdx.x == 0) g_total = 0;
        int i = (blockIdx.x - DOUT) * 128 + threadIdx.x;
        if (i < n) g_deg[i] = 0;
    }
}

// ---------------- Cholesky: 512 threads, 4 per row, pitch-129 smem ----------
static constexpr int CP_ = 129;
static constexpr int CHOL_SMEM = (DOUT * CP_ + DOUT) * 4;   // 66560 B

__global__ void __launch_bounds__(512) k_chol() {
    extern __shared__ float s[];
    float* diag = s + DOUT * CP_;
    int tid = threadIdx.x;
    int t = tid >> 2;        // row 0..127
    int q = tid & 3;         // column-quarter within row
    for (int idx = tid; idx < DOUT * DOUT; idx += 512) {
        int r = idx >> 7, c = idx & 127;
        s[r * CP_ + c] = g_G[idx];
    }
    __syncthreads();
    for (int k = 0; k < DOUT; k++) {
        float dk = sqrtf(s[k * CP_ + k]);
        if (tid == 0) diag[k] = dk;
        if (q == 0 && t > k) s[t * CP_ + k] /= dk;
        __syncthreads();
        if (t > k) {
            float lik = s[t * CP_ + k];
            for (int j = k + 1 + q; j <= t; j += 4)
                s[t * CP_ + j] -= lik * s[j * CP_ + k];
        }
        __syncthreads();
    }
    for (int idx = tid; idx < DOUT * DOUT; idx += 512) {
        int r = idx >> 7, c = idx & 127;
        g_G[idx] = (r == c) ? diag[r] : s[r * CP_ + c];
    }
}

// ---------------- inv(L): warp/column, register daxpy sweep ------------------
// Column j: lane owns rows r = lane + 32u with register partial sums.
// Per step: uniform acc-select, 1 shfl broadcast, <=4 conflict-free fma.
static constexpr int LINV_SMEM = (DOUT * CP_ + DOUT) * 4;  // Ls + rdiag

__global__ void __launch_bounds__(512) k_linv() {
    extern __shared__ float s[];
    float* Ls = s;                       // 128 x pitch129 (L, true diag)
    float* rd = s + DOUT * CP_;          // 1/diag
    int tid = threadIdx.x;
    int wid = tid >> 5, lane = tid & 31;
    for (int idx = tid; idx < DOUT * DOUT; idx += 512) {
        int r = idx >> 7, c = idx & 127;
        Ls[r * CP_ + c] = g_G[idx];
    }
    if (tid < DOUT) rd[tid] = 1.f / g_G[tid * DOUT + tid];
    __syncthreads();

    int j = blockIdx.x * 16 + wid;       // this warp's column
    // zero the upper part of column j (rows < j)
    for (int i = lane; i < j; i += 32) g_Minv[i * DOUT + j] = 0.f;

    float acc0 = 0.f, acc1 = 0.f, acc2 = 0.f, acc3 = 0.f;
    int r0 = lane, r1 = lane + 32, r2 = lane + 64, r3 = lane + 96;

    for (int i = j; i < DOUT; i++) {
        float mval;
        if (i == j) {
            mval = rd[j];
        } else {
            int u = i >> 5;              // uniform across warp
            float a = (u == 0) ? acc0 : (u == 1) ? acc1 : (u == 2) ? acc2 : acc3;
            mval = -__shfl_sync(0xffffffffu, a, i & 31) * rd[i];
        }
        if (lane == (i & 31)) g_Minv[i * DOUT + j] = mval;
        if (r0 > i) acc0 = fmaf(Ls[r0 * CP_ + i], mval, acc0);
        if (r1 > i) acc1 = fmaf(Ls[r1 * CP_ + i], mval, acc1);
        if (r2 > i) acc2 = fmaf(Ls[r2 * CP_ + i], mval, acc2);
        if (r3 > i) acc3 = fmaf(Ls[r3 * CP_ + i], mval, acc3);
    }
}

// ---------------- W_ortho = W @ inv(L)^T  (free-order, 16 blocks) -----------
// W_ortho[r][j] = sum_{k<=j} W[r][k] * M[j][k];  emit bf16 hi/lo at [n=j][k=r].
static constexpr int WP_ = 132;                       // W smem pitch (floats)
static constexpr int WO_SMEM = (DOUT * CP_ + 32 * WP_) * 4;   // 82944 B

__global__ void __launch_bounds__(256) k_wortho(const float* __restrict__ W) {
    extern __shared__ float s[];
    float* Ms = s;                  // 128 x pitch129 (inv(L))
    float* Ws = s + DOUT * CP_;     // 32 rows x pitch132
    int tid = threadIdx.x;
    int r0 = blockIdx.x * 32;

    for (int idx = tid; idx < DOUT * DOUT; idx += 256) {
        int r = idx >> 7, c = idx & 127;
        Ms[r * CP_ + c] = g_Minv[idx];
    }
    for (int idx = tid; idx < 32 * DOUT; idx += 256) {
        int rl = idx >> 7, c = idx & 127;
        Ws[rl * WP_ + c] = W[(size_t)(r0 + rl) * DOUT + c];
    }
    __syncthreads();

    int rl = tid >> 3;              // 0..31 local row
    int jq = tid & 7;               // j = jq + 8*jj  (conflict-free across warp)
    int r = r0 + rl;
    const float* wrow = Ws + rl * WP_;
    for (int jj = 0; jj < 16; jj++) {
        int j = jq + 8 * jj;
        const float* mrow = Ms + j * CP_;
        float s0 = 0.f, s1 = 0.f, s2 = 0.f, s3 = 0.f;
        int k = 0;
        for (; k + 3 <= j; k += 4) {
            s0 = fmaf(wrow[k],     mrow[k],     s0);
            s1 = fmaf(wrow[k + 1], mrow[k + 1], s1);
            s2 = fmaf(wrow[k + 2], mrow[k + 2], s2);
            s3 = fmaf(wrow[k + 3], mrow[k + 3], s3);
        }
        for (; k <= j; k++) s0 = fmaf(wrow[k], mrow[k], s0);
        float sv = (s0 + s1) + (s2 + s3);
        __nv_bfloat16 h = __float2bfloat16_rn(sv);
        g_wth[j * DIN + r] = h;
        g_wtl[j * DIN + r] = __float2bfloat16_rn(sv - __bfloat162float(h));
    }
}

// ---------------- GEMM: Xp = X @ W_ortho  (mma.sync bf16 hi/lo split) -------
static constexpr int TILE_B  = 128 * 64;            // 8192
static constexpr int STAGE_B = 4 * TILE_B;          // 32768 (Ah, Al, Bh, Bl)
static constexpr int GEMM_SMEM = 2 * STAGE_B;       // 65536

__global__ void __launch_bounds__(256, 2)
k_gemm(const float* __restrict__ X, int nn) {
    extern __shared__ char smem[];
    uint32_t sm0 = smem_u32(smem);
    int tid  = threadIdx.x;
    int lane = tid & 31;
    int wid  = tid >> 5;
    int warpm = wid & 3;
    int warpn = wid >> 2;
    int m0 = blockIdx.x * 128;

    float d[2][8][4];
    #pragma unroll
    for (int mf = 0; mf < 2; mf++)
        #pragma unroll
        for (int nf = 0; nf < 8; nf++)
            #pragma unroll
            for (int q = 0; q < 4; q++) d[mf][nf][q] = 0.f;

    int srow[4], skq[4];
    #pragma unroll
    for (int t = 0; t < 4; t++) {
        int idx = tid + t * 256;
        srow[t] = idx >> 3;
        skq[t]  = (idx & 7) << 2;
    }
    int brow[2], bq[2];
    #pragma unroll
    for (int t = 0; t < 2; t++) {
        int idx = tid + t * 256;
        brow[t] = idx >> 2;
        bq[t]   = (idx & 3) * 16;
    }

    uint32_t aoff[2][2];
    {
        int arow = warpm * 32 + ((lane >> 3) & 1) * 8 + (lane & 7);
        int akb  = (lane >> 4) << 4;
        #pragma unroll
        for (int mf = 0; mf < 2; mf++)
            #pragma unroll
            for (int ks = 0; ks < 2; ks++)
                aoff[mf][ks] = swz((uint32_t)((arow + mf * 16) * 64 + ks * 32 + akb));
    }
    uint32_t boff[4][2];
    {
        int bn  = warpn * 64 + ((lane >= 16) ? 8 : 0) + (lane & 7);
        int bkb = ((lane >> 3) & 1) * 16;
        #pragma unroll
        for (int np = 0; np < 4; np++)
            #pragma unroll
            for (int ks = 0; ks < 2; ks++)
                boff[np][ks] = swz((uint32_t)((bn + np * 16) * 64 + ks * 32 + bkb));
    }

    // ---- prologue: chunk 0 ----
    {
        uint32_t sBh = sm0 + 2 * TILE_B, sBl = sm0 + 3 * TILE_B;
        #pragma unroll
        for (int t = 0; t < 2; t++) {
            uint32_t off = swz((uint32_t)(brow[t] * 64 + bq[t]));
            cp16(sBh + off, (const char*)(g_wth + (size_t)brow[t] * DIN) + bq[t]);
            cp16(sBl + off, (const char*)(g_wtl + (size_t)brow[t] * DIN) + bq[t]);
        }
        CP_COMMIT();
        #pragma unroll
        for (int t = 0; t < 4; t++) {
            int row = srow[t], kq = skq[t];
            int m = m0 + row;
            float4 xv = make_float4(0.f, 0.f, 0.f, 0.f);
            if (m < nn) xv = *(const float4*)(X + (size_t)m * DIN + kq);
            __nv_bfloat16 h0 = __float2bfloat16_rn(xv.x), h1 = __float2bfloat16_rn(xv.y);
            __nv_bfloat16 h2 = __float2bfloat16_rn(xv.z), h3 = __float2bfloat16_rn(xv.w);
            uint2 hv; hv.x = pack_bf16(h0, h1); hv.y = pack_bf16(h2, h3);
            uint2 lv;
            lv.x = pack_bf16(__float2bfloat16_rn(xv.x - __bfloat162float(h0)),
                             __float2bfloat16_rn(xv.y - __bfloat162float(h1)));
            lv.y = pack_bf16(__float2bfloat16_rn(xv.z - __bfloat162float(h2)),
                             __float2bfloat16_rn(xv.w - __bfloat162float(h3)));
            uint32_t off = swz((uint32_t)(row * 64 + kq * 2));
            *(uint64_t*)(smem + off)          = *(uint64_t*)&hv;
            *(uint64_t*)(smem + TILE_B + off) = *(uint64_t*)&lv;
        }
        CP_WAIT0();
    }
    __syncthreads();

    #pragma unroll 1
    for (int c = 0; c < 16; c++) {
        int s = c & 1;
        float4 areg[4];
        if (c < 15) {
            int koff = (c + 1) * 32;
            uint32_t nst = sm0 + (uint32_t)(s ^ 1) * STAGE_B;
            #pragma unroll
            for (int t = 0; t < 2; t++) {
                uint32_t off = swz((uint32_t)(brow[t] * 64 + bq[t]));
                cp16(nst + 2 * TILE_B + off,
                     (const char*)(g_wth + (size_t)brow[t] * DIN + koff) + bq[t]);
                cp16(nst + 3 * TILE_B + off,
                     (const char*)(g_wtl + (size_t)brow[t] * DIN + koff) + bq[t]);
            }
            CP_COMMIT();
            #pragma unroll
            for (int t = 0; t < 4; t++) {
                int m = m0 + srow[t];
                areg[t] = make_float4(0.f, 0.f, 0.f, 0.f);
                if (m < nn) areg[t] = *(const float4*)(X + (size_t)m * DIN + koff + skq[t]);
            }
        }

        uint32_t stb = sm0 + (uint32_t)s * STAGE_B;
        #pragma unroll
        for (int ks = 0; ks < 2; ks++) {
            uint32_t ahf[2][4], alf[2][4];
            #pragma unroll
            for (int mf = 0; mf < 2; mf++) {
                ldm_x4(ahf[mf], stb + aoff[mf][ks]);
                ldm_x4(alf[mf], stb + TILE_B + aoff[mf][ks]);
            }
            #pragma unroll
            for (int np = 0; np < 4; np++) {
                uint32_t bh4[4], bl4[4];
                ldm_x4(bh4, stb + 2 * TILE_B + boff[np][ks]);
                ldm_x4(bl4, stb + 3 * TILE_B + boff[np][ks]);
                #pragma unroll
                for (int sub = 0; sub < 2; sub++) {
                    int nf = np * 2 + sub;
                    #pragma unroll
                    for (int mf = 0; mf < 2; mf++) {
                        mma16816(d[mf][nf], ahf[mf], bh4 + 2 * sub);
                        mma16816(d[mf][nf], ahf[mf], bl4 + 2 * sub);
                        mma16816(d[mf][nf], alf[mf], bh4 + 2 * sub);
                    }
                }
            }
        }

        if (c < 15) {
            char* st = smem + (size_t)(s ^ 1) * STAGE_B;
            #pragma unroll
            for (int t = 0; t < 4; t++) {
                int row = srow[t], kq = skq[t];
                float4 xv = areg[t];
                __nv_bfloat16 h0 = __float2bfloat16_rn(xv.x), h1 = __float2bfloat16_rn(xv.y);
                __nv_bfloat16 h2 = __float2bfloat16_rn(xv.z), h3 = __float2bfloat16_rn(xv.w);
                uint2 hv; hv.x = pack_bf16(h0, h1); hv.y = pack_bf16(h2, h3);
                uint2 lv;
                lv.x = pack_bf16(__float2bfloat16_rn(xv.x - __bfloat162float(h0)),
                                 __float2bfloat16_rn(xv.y - __bfloat162float(h1)));
                lv.y = pack_bf16(__float2bfloat16_rn(xv.z - __bfloat162float(h2)),
                                 __float2bfloat16_rn(xv.w - __bfloat162float(h3)));
                uint32_t off = swz((uint32_t)(row * 64 + kq * 2));
                *(uint64_t*)(st + off)          = *(uint64_t*)&hv;
                *(uint64_t*)(st + TILE_B + off) = *(uint64_t*)&lv;
            }
        }
        CP_WAIT0();
        __syncthreads();
    }

    // ---- epilogue: write Xp as fp16 ----
    int qrow = lane >> 2;
    #pragma unroll
    for (int mf = 0; mf < 2; mf++) {
        int r0 = m0 + warpm * 32 + mf * 16 + qrow;
        #pragma unroll
        for (int nf = 0; nf < 8; nf++) {
            int col = warpn * 64 + nf * 8 + (lane & 3) * 2;
            if (r0 < nn)
                *(__half2*)(g_xph + (size_t)r0 * DOUT + col) =
                    __floats2half2_rn(d[mf][nf][0], d[mf][nf][1]);
            if (r0 + 8 < nn)
                *(__half2*)(g_xph + (size_t)(r0 + 8) * DOUT + col) =
                    __floats2half2_rn(d[mf][nf][2], d[mf][nf][3]);
        }
    }
}

// ---------------- CSR build --------------------------------------------------
__global__ void k_hist(const int* __restrict__ rows, int ne) {
    int i = blockIdx.x * blockDim.x + threadIdx.x;
    int b = i * 4;
    if (b + 3 < ne) {
        int4 r = *(const int4*)(rows + b);
        atomicAdd(&g_deg[r.x], 1);
        atomicAdd(&g_deg[r.y], 1);
        atomicAdd(&g_deg[r.z], 1);
        atomicAdd(&g_deg[r.w], 1);
    } else {
        for (int e = b; e < ne; e++) atomicAdd(&g_deg[rows[e]], 1);
    }
}

// row-base allocation: warp-aggregated atomic; seeds cursor with the base
__global__ void k_alloc(int n) {
    int i = blockIdx.x * blockDim.x + threadIdx.x;
    int lane = threadIdx.x & 31;
    int d = (i < n) ? g_deg[i] : 0;
    int incl = d;
    #pragma unroll
    for (int o = 1; o < 32; o <<= 1) {
        int v = __shfl_up_sync(0xffffffffu, incl, o);
        if (lane >= o) incl += v;
    }
    int wsum = __shfl_sync(0xffffffffu, incl, 31);
    int base = 0;
    if (lane == 31 && wsum > 0) base = atomicAdd(&g_total, wsum);
    base = __shfl_sync(0xffffffffu, base, 31);
    if (i < n) {
        int rp = base + incl - d;
        g_rowptr[i] = rp;
        g_cursor[i] = rp;
    }
}

__global__ void k_scatter(const int* __restrict__ rows, const int* __restrict__ cols,
                          const float* __restrict__ vals, int ne) {
    int i = blockIdx.x * blockDim.x + threadIdx.x;
    int b = i * 4;
    if (b + 3 < ne) {
        int4   r = *(const int4*)(rows + b);
        int4   c = *(const int4*)(cols + b);
        float4 v = *(const float4*)(vals + b);
        int p0 = atomicAdd(&g_cursor[r.x], 1);
        g_edge[p0] = make_int2(c.x, __float_as_int(v.x));
        int p1 = atomicAdd(&g_cursor[r.y], 1);
        g_edge[p1] = make_int2(c.y, __float_as_int(v.y));
        int p2 = atomicAdd(&g_cursor[r.z], 1);
        g_edge[p2] = make_int2(c.z, __float_as_int(v.z));
        int p3 = atomicAdd(&g_cursor[r.w], 1);
        g_edge[p3] = make_int2(c.w, __float_as_int(v.w));
    } else {
        for (int e = b; e < ne; e++) {
            int pos = atomicAdd(&g_cursor[rows[e]], 1);
            g_edge[pos] = make_int2(cols[e], __float_as_int(vals[e]));
        }
    }
}

// ---------------- SpMM + tanh: warp per row, fp16 gathers, MLP=4 ------------
__global__ void __launch_bounds__(256) k_spmm(float* __restrict__ out, int n) {
    int warp = (blockIdx.x * blockDim.x + threadIdx.x) >> 5;
    int lane = threadIdx.x & 31;
    if (warp >= n) return;
    int beg = g_rowptr[warp];
    int end = beg + g_deg[warp];
    const __half* xpb = g_xph + lane * 4;
    float4 acc = make_float4(0.f, 0.f, 0.f, 0.f);
    for (int b = beg; b < end; b += 32) {
        int idx = b + lane;
        int cc = 0; float vv = 0.f;
        if (idx < end) {
            int2 e = __ldg(&g_edge[idx]);
            cc = e.x; vv = __int_as_float(e.y);
        }
        int cnt = min(32, end - b);
        int cnt4 = (cnt + 3) & ~3;
        for (int j = 0; j < cnt4; j += 4) {
            int   c0 = __shfl_sync(0xffffffffu, cc, j);
            int   c1 = __shfl_sync(0xffffffffu, cc, j + 1);
            int   c2 = __shfl_sync(0xffffffffu, cc, j + 2);
            int   c3 = __shfl_sync(0xffffffffu, cc, j + 3);
            float v0 = __shfl_sync(0xffffffffu, vv, j);
            float v1 = __shfl_sync(0xffffffffu, vv, j + 1);
            float v2 = __shfl_sync(0xffffffffu, vv, j + 2);
            float v3 = __shfl_sync(0xffffffffu, vv, j + 3);
            uint2 h0 = __ldg((const uint2*)(xpb + (size_t)c0 * DOUT));
            uint2 h1 = __ldg((const uint2*)(xpb + (size_t)c1 * DOUT));
            uint2 h2 = __ldg((const uint2*)(xpb + (size_t)c2 * DOUT));
            uint2 h3 = __ldg((const uint2*)(xpb + (size_t)c3 * DOUT));
            float2 a0 = __half22float2(*(__half2*)&h0.x), b0 = __half22float2(*(__half2*)&h0.y);
            float2 a1 = __half22float2(*(__half2*)&h1.x), b1 = __half22float2(*(__half2*)&h1.y);
            float2 a2 = __half22float2(*(__half2*)&h2.x), b2 = __half22float2(*(__half2*)&h2.y);
            float2 a3 = __half22float2(*(__half2*)&h3.x), b3 = __half22float2(*(__half2*)&h3.y);
            acc.x = fmaf(v0, a0.x, acc.x); acc.y = fmaf(v0, a0.y, acc.y);
            acc.z = fmaf(v0, b0.x, acc.z); acc.w = fmaf(v0, b0.y, acc.w);
            acc.x = fmaf(v1, a1.x, acc.x); acc.y = fmaf(v1, a1.y, acc.y);
            acc.z = fmaf(v1, b1.x, acc.z); acc.w = fmaf(v1, b1.y, acc.w);
            acc.x = fmaf(v2, a2.x, acc.x); acc.y = fmaf(v2, a2.y, acc.y);
            acc.z = fmaf(v2, b2.x, acc.z); acc.w = fmaf(v2, b2.y, acc.w);
            acc.x = fmaf(v3, a3.x, acc.x); acc.y = fmaf(v3, a3.y, acc.y);
            acc.z = fmaf(v3, b3.x, acc.z); acc.w = fmaf(v3, b3.y, acc.w);
        }
    }
    float4 o;
    o.x = tanhf(acc.x); o.y = tanhf(acc.y);
    o.z = tanhf(acc.z); o.w = tanhf(acc.w);
    *(float4*)(out + (size_t)warp * DOUT + lane * 4) = o;
}

// ---------------- launch (single stream) -------------------------------------
extern "C" void kernel_launch(void* const* d_in, const int* in_sizes, int n_in,
                              void* d_out, int out_size) {
    const float* X    = (const float*)d_in[0];   // [N, 512]
    const float* W    = (const float*)d_in[1];   // [512, 128]
    const float* vals = (const float*)d_in[2];   // [E]
    const int*   rows = (const int*)d_in[3];     // [E]
    const int*   cols = (const int*)d_in[4];     // [E]
    float* out = (float*)d_out;

    int nn = in_sizes[0] / DIN;
    int ne = in_sizes[2];

    cudaFuncSetAttribute(k_chol,   cudaFuncAttributeMaxDynamicSharedMemorySize, CHOL_SMEM);
    cudaFuncSetAttribute(k_linv,   cudaFuncAttributeMaxDynamicSharedMemorySize, LINV_SMEM);
    cudaFuncSetAttribute(k_wortho, cudaFuncAttributeMaxDynamicSharedMemorySize, WO_SMEM);
    cudaFuncSetAttribute(k_gemm,   cudaFuncAttributeMaxDynamicSharedMemorySize, GEMM_SMEM);

    int zblocks = (nn + 127) / 128;
    int e4 = (ne + 3) / 4;

    // ncu lands on launch index 3 -> k_linv profiled (verify daxpy rewrite)
    kA<<<DOUT + zblocks, 128>>>(W, nn);                          // 0
    k_chol<<<1, 512, CHOL_SMEM>>>();                             // 1
    k_hist<<<(e4 + 255) / 256, 256>>>(rows, ne);                 // 2
    k_linv<<<8, 512, LINV_SMEM>>>();                             // 3  <- profiled
    k_wortho<<<16, 256, WO_SMEM>>>(W);                           // 4
    k_alloc<<<(nn + 255) / 256, 256>>>(nn);                      // 5
    k_gemm<<<(nn + 127) / 128, 256, GEMM_SMEM>>>(X, nn);         // 6
    k_scatter<<<(e4 + 255) / 256, 256>>>(rows, cols, vals, ne);  // 7
    k_spmm<<<(nn * 32 + 255) / 256, 256>>>(out, nn);             // 8
}